// round 16
// baseline (speedup 1.0000x reference)
#include <cuda_runtime.h>
#include <cuda_fp16.h>
#include <math.h>
#include <stdint.h>

// ---------------- problem constants ----------------
#define NROWS   131072
#define DDIM    256
#define NCODES  1024
#define EPSC    1e-5f
#define DECAYC  0.99f

// ---------------- output layout (float32, reference tuple order, flattened) ----------------
#define OFF_ZQST 0ULL
#define OFF_ZID  33554432ULL
#define OFF_LOSS 33685504ULL
#define OFF_ZQ   33685505ULL
#define OFF_NEMB 67239937ULL
#define OFF_NCS  67502081ULL
#define OFF_NEA  67503105ULL
#define OFF_PPL  67765249ULL

#define CORR_SCALE 1024.0f
#define CORR_INV   0.0009765625f   // 2^-10

// ---------------- device scratch (static: no allocation allowed) ----------------
static __device__ __half g_h0[NROWS * DDIM];    // fp16(normalized h)
static __device__ __half g_h1[NROWS * DDIM];    // fp16((hn - h0) * 2^10)
static __device__ __half g_e0[NCODES * DDIM];   // fp16(normalized embed)
static __device__ __half g_e1[NCODES * DDIM];   // fp16((en - e0) * 2^10)
static __device__ int    g_zid[NROWS];
static __device__ int    g_icnt[NCODES];        // int histogram of z_id
static __device__ int    g_cursor[NCODES];      // prefix offsets -> end offsets
static __device__ int    g_csr[NROWS];          // row ids grouped by code
static __device__ float  g_esum[NCODES * DDIM];
static __device__ double g_losspart[16384];
static __device__ float  g_den[NCODES];
static __device__ int    g_src[NCODES];

// ---------------- smem layout for argmin kernel ----------------
#define A_BASE   0u
#define B_BASE   131072u
#define RV_OFF   196608u
#define RI_OFF   198656u
#define SMEM_DYN 200704u

// ---------------- PTX helpers (baseline sm_80+ features only) ----------------
__device__ __forceinline__ uint32_t smem_u32(const void* p) {
    uint32_t a;
    asm("{ .reg .u64 t; cvta.to.shared.u64 t, %1; cvt.u32.u64 %0, t; }" : "=r"(a) : "l"(p));
    return a;
}
__device__ __forceinline__ void cpa16(uint32_t dst, const void* src) {
    asm volatile("cp.async.cg.shared.global [%0], [%1], 16;" :: "r"(dst), "l"(src) : "memory");
}
#define CP_COMMIT() asm volatile("cp.async.commit_group;" ::: "memory")
#define CP_WAIT0()  asm volatile("cp.async.wait_group 0;" ::: "memory")

__device__ __forceinline__ void ldmx4(uint32_t* r, uint32_t addr) {
    asm volatile("ldmatrix.sync.aligned.m8n8.x4.shared.b16 {%0,%1,%2,%3}, [%4];"
        : "=r"(r[0]), "=r"(r[1]), "=r"(r[2]), "=r"(r[3]) : "r"(addr));
}
__device__ __forceinline__ void hmma(float* c, const uint32_t* a, const uint32_t* b) {
    asm volatile("mma.sync.aligned.m16n8k16.row.col.f32.f16.f16.f32 "
        "{%0,%1,%2,%3}, {%4,%5,%6,%7}, {%8,%9}, {%0,%1,%2,%3};"
        : "+f"(c[0]), "+f"(c[1]), "+f"(c[2]), "+f"(c[3])
        : "r"(a[0]), "r"(a[1]), "r"(a[2]), "r"(a[3]), "r"(b[0]), "r"(b[1]));
}
// 16B-granule XOR swizzle within 128B rows (conflict-free ldmatrix)
__device__ __forceinline__ uint32_t swzoff(int r, int ci) {
    uint32_t o = (uint32_t)(r * 128 + ci * 16);
    return o ^ ((o >> 3) & 0x70);
}

// ---------------- threefry / jax randint ----------------
__device__ __forceinline__ unsigned rotl32(unsigned x, int r) { return (x << r) | (x >> (32 - r)); }
__device__ __forceinline__ void tf2x32(unsigned k0, unsigned k1, unsigned& x0, unsigned& x1) {
    const unsigned ks2 = 0x1BD11BDAu ^ k0 ^ k1;
#define TF_RND(r) { x0 += x1; x1 = rotl32(x1, (r)); x1 ^= x0; }
    x0 += k0; x1 += k1;
    TF_RND(13) TF_RND(15) TF_RND(26) TF_RND(6)
    x0 += k1;  x1 += ks2 + 1u;
    TF_RND(17) TF_RND(29) TF_RND(16) TF_RND(24)
    x0 += ks2; x1 += k0 + 2u;
    TF_RND(13) TF_RND(15) TF_RND(26) TF_RND(6)
    x0 += k0;  x1 += k1 + 3u;
    TF_RND(17) TF_RND(29) TF_RND(16) TF_RND(24)
    x0 += k1;  x1 += ks2 + 4u;
    TF_RND(13) TF_RND(15) TF_RND(26) TF_RND(6)
    x0 += ks2; x1 += k0 + 5u;
#undef TF_RND
}
__device__ unsigned jax_randint_idx(int i) {
    unsigned s0 = 0u, s1 = 1u;
    tf2x32(0u, 42u, s0, s1);
    unsigned x0 = 0u, x1 = (unsigned)i;
    tf2x32(s0, s1, x0, x1);
    return (x0 ^ x1) & 0x1FFFFu;
}

// ---------------- fp16 scaled double split ----------------
__device__ __forceinline__ void hsplit(float a, unsigned short& u0, unsigned short& u1) {
    __half p0 = __float2half_rn(a);
    float r = a - __half2float(p0);
    __half p1 = __float2half_rn(r * CORR_SCALE);
    u0 = __half_as_ushort(p0);
    u1 = __half_as_ushort(p1);
}

// ---------------- simple kernels ----------------
__global__ void k_zero() {
    int i = threadIdx.x;           // 1 block x 1024
    g_icnt[i] = 0;
}

// normalize h rows and write scaled fp16 splits (warp per row) — bit-exact norm order
__global__ void k_prep_h(const float* __restrict__ h) {
    int w = (blockIdx.x * blockDim.x + threadIdx.x) >> 5;
    int lane = threadIdx.x & 31;
    if (w >= NROWS) return;
    const float4* row = (const float4*)(h + (size_t)w * DDIM);
    float4 v[2];
    float s = 0.0f;
#pragma unroll
    for (int t = 0; t < 2; t++) {
        v[t] = row[lane + 32 * t];
        s += v[t].x * v[t].x + v[t].y * v[t].y + v[t].z * v[t].z + v[t].w * v[t].w;
    }
#pragma unroll
    for (int o = 16; o; o >>= 1) s += __shfl_xor_sync(0xFFFFFFFFu, s, o);
    float rs = (float)(1.0 / sqrt((double)fmaxf(s, 1e-12f)));
#pragma unroll
    for (int t = 0; t < 2; t++) {
        int f = lane + 32 * t;
        float a[4] = { v[t].x * rs, v[t].y * rs, v[t].z * rs, v[t].w * rs };
        unsigned short u0[4], u1[4];
#pragma unroll
        for (int e = 0; e < 4; e++) hsplit(a[e], u0[e], u1[e]);
        size_t off = (size_t)w * DDIM + f * 4;
        *(uint2*)(g_h0 + off) = make_uint2((uint32_t)u0[0] | ((uint32_t)u0[1] << 16),
                                           (uint32_t)u0[2] | ((uint32_t)u0[3] << 16));
        *(uint2*)(g_h1 + off) = make_uint2((uint32_t)u1[0] | ((uint32_t)u1[1] << 16),
                                           (uint32_t)u1[2] | ((uint32_t)u1[3] << 16));
    }
}

// normalize embed rows and write scaled fp16 splits
__global__ void k_prep_embed(const float* __restrict__ e) {
    int w = (blockIdx.x * blockDim.x + threadIdx.x) >> 5;
    int lane = threadIdx.x & 31;
    if (w >= NCODES) return;
    const float* row = e + (size_t)w * DDIM;
    float s = 0.0f;
#pragma unroll
    for (int t = 0; t < 8; t++) { float v = row[lane + 32 * t]; s += v * v; }
#pragma unroll
    for (int o = 16; o; o >>= 1) s += __shfl_xor_sync(0xFFFFFFFFu, s, o);
    float rs = (float)(1.0 / sqrt((double)fmaxf(s, 1e-12f)));
#pragma unroll
    for (int t = 0; t < 8; t++) {
        int d = lane + 32 * t;
        unsigned short u0, u1;
        hsplit(row[d] * rs, u0, u1);
        size_t idx = (size_t)w * DDIM + d;
        g_e0[idx] = __ushort_as_half(u0);
        g_e1[idx] = __ushort_as_half(u1);
    }
}

// ---------------- HMMA argmin GEMM: A persistent in smem, B streamed ----------------
__device__ __forceinline__ void issue_B(int tid, int s2, uint32_t smem_base) {
    const int cc = s2 >> 2, kt = s2 & 3;
    uint32_t buf = smem_base + B_BASE + (uint32_t)(s2 & 1) * 32768u;
    const __half* eb[2] = { g_e0, g_e1 };
#pragma unroll
    for (int t = 0; t < 2; t++) {
#pragma unroll
        for (int q = 0; q < 2; q++) {
            int idx = tid + 512 * q;           // 1024 granules of 16B per split
            int r = idx >> 3, ci = idx & 7;
            cpa16(buf + t * 16384u + swzoff(r, ci),
                  eb[t] + (size_t)(cc * 128 + r) * DDIM + kt * 64 + ci * 8);
        }
    }
}

__global__ __launch_bounds__(512, 1) void k_argmin_mma(float* __restrict__ out) {
    extern __shared__ __align__(1024) char smem[];
    const uint32_t sb = smem_u32(smem);
    const int tid = threadIdx.x, lane = tid & 31, w = tid >> 5;
    const size_t rowBase = (size_t)blockIdx.x * 128;

    // prologue: persistent A (4 kt-tiles x 2 splits = 128KB), then stage-0 B
    {
        const __half* hb[2] = { g_h0, g_h1 };
#pragma unroll
        for (int g = 0; g < 16; g++) {
            int idx = tid + 512 * g;               // 8192 granules total
            int kt = idx >> 11, sp = (idx >> 10) & 1;
            int r = (idx & 1023) >> 3, ci = idx & 7;
            cpa16(sb + A_BASE + (uint32_t)(kt * 2 + sp) * 16384u + swzoff(r, ci),
                  hb[sp] + (rowBase + r) * DDIM + kt * 64 + ci * 8);
        }
    }
    issue_B(tid, 0, sb);
    CP_COMMIT(); CP_WAIT0(); __syncthreads();

    const int mbase = (w & 3) * 32;    // warp's 32 rows within 128
    const int nbw   = (w >> 2) * 32;   // warp's 32 codes within 128-chunk

    float accM[2][4][4], accC[2][4][4];
    float bestV[4]; int bestI[4];
#pragma unroll
    for (int b = 0; b < 4; b++) { bestV[b] = 3.4e38f; bestI[b] = 0; }

    const int arow = mbase + (lane & 7) + ((lane >> 3) & 1) * 8;
    const int aciX = (lane >> 4);
    const int brow = nbw + (lane & 7) + ((lane >> 4) << 3);
    const int bciX = ((lane >> 3) & 1);

    for (int s = 0; s < 32; s++) {              // s = cc*4 + kt
        const uint32_t bufB = sb + B_BASE + (uint32_t)(s & 1) * 32768u;
        const uint32_t bufA = sb + A_BASE + (uint32_t)((s & 3) * 2) * 16384u;
        if ((s & 3) == 0) {
#pragma unroll
            for (int mi = 0; mi < 2; mi++)
#pragma unroll
                for (int nj = 0; nj < 4; nj++)
#pragma unroll
                    for (int rr = 0; rr < 4; rr++) { accM[mi][nj][rr] = 0.0f; accC[mi][nj][rr] = 0.0f; }
        }
        if (s < 31) {
            issue_B(tid, s + 1, sb);
            CP_COMMIT();
        }

#pragma unroll
        for (int ks = 0; ks < 4; ks++) {
            uint32_t Aoff = swzoff(arow, ks * 2 + aciX);
            uint32_t A[2][2][4];
#pragma unroll
            for (int t = 0; t < 2; t++) {
                ldmx4(A[t][0], bufA + t * 16384u + Aoff);
                ldmx4(A[t][1], bufA + t * 16384u + Aoff + 2048u);
            }
            uint32_t Boff = swzoff(brow, ks * 2 + bciX);
            uint32_t B0a[4], B0b[4], B1a[4], B1b[4];
            ldmx4(B0a, bufB + Boff);
            ldmx4(B0b, bufB + Boff + 2048u);
            ldmx4(B1a, bufB + 16384u + Boff);
            ldmx4(B1b, bufB + 16384u + Boff + 2048u);
#pragma unroll
            for (int nj = 0; nj < 4; nj++) {
                const uint32_t* b0 = (nj < 2 ? B0a : B0b) + (nj & 1) * 2;
                const uint32_t* b1 = (nj < 2 ? B1a : B1b) + (nj & 1) * 2;
#pragma unroll
                for (int mi = 0; mi < 2; mi++) {
                    hmma(accM[mi][nj], A[0][mi], b0);
                    hmma(accC[mi][nj], A[0][mi], b1);
                    hmma(accC[mi][nj], A[1][mi], b0);
                }
            }
        }

        if ((s & 3) == 3) {                 // chunk done: fold argmin
            const int cc = s >> 2;
#pragma unroll
            for (int mi = 0; mi < 2; mi++)
#pragma unroll
                for (int nj = 0; nj < 4; nj++) {
                    int col0 = cc * 128 + nbw + nj * 8 + (lane & 3) * 2;
                    float d0 = 1.0f - (accM[mi][nj][0] + accC[mi][nj][0] * CORR_INV);
                    float d1 = 1.0f - (accM[mi][nj][1] + accC[mi][nj][1] * CORR_INV);
                    float d2 = 1.0f - (accM[mi][nj][2] + accC[mi][nj][2] * CORR_INV);
                    float d3 = 1.0f - (accM[mi][nj][3] + accC[mi][nj][3] * CORR_INV);
                    int b0 = 2 * mi, b1 = 2 * mi + 1;
                    if (d0 < bestV[b0]) { bestV[b0] = d0; bestI[b0] = col0; }
                    if (d1 < bestV[b0]) { bestV[b0] = d1; bestI[b0] = col0 + 1; }
                    if (d2 < bestV[b1]) { bestV[b1] = d2; bestI[b1] = col0; }
                    if (d3 < bestV[b1]) { bestV[b1] = d3; bestI[b1] = col0 + 1; }
                }
        }

        if (s < 31) { CP_WAIT0(); __syncthreads(); }
    }

    // quad reduce: lanes 4q..4q+3 share the same rows, different cols
#pragma unroll
    for (int off = 1; off <= 2; off <<= 1) {
#pragma unroll
        for (int b = 0; b < 4; b++) {
            float v = __shfl_down_sync(0xFFFFFFFFu, bestV[b], off);
            int   i = __shfl_down_sync(0xFFFFFFFFu, bestI[b], off);
            if (v < bestV[b] || (v == bestV[b] && i < bestI[b])) { bestV[b] = v; bestI[b] = i; }
        }
    }
    float* redV = (float*)(smem + RV_OFF);          // 128 rows x 4 nwarps
    int*   redI = (int*)(smem + RI_OFF);
    if ((lane & 3) == 0) {
#pragma unroll
        for (int b = 0; b < 4; b++) {
            int row = mbase + (b >> 1) * 16 + (lane >> 2) + (b & 1) * 8;
            int nw = w >> 2;
            redV[row * 4 + nw] = bestV[b];
            redI[row * 4 + nw] = bestI[b];
        }
    }
    __syncthreads();
    if (tid < 128) {
        float bv = redV[tid * 4]; int bi = redI[tid * 4];
#pragma unroll
        for (int t = 1; t < 4; t++) {
            float v = redV[tid * 4 + t]; int ix = redI[tid * 4 + t];
            if (v < bv || (v == bv && ix < bi)) { bv = v; bi = ix; }
        }
        g_zid[rowBase + tid] = bi;
        out[OFF_ZID + rowBase + tid] = (float)bi;
        atomicAdd(&g_icnt[bi], 1);      // fused count
    }
}

// ---------------- CSR build: prefix -> fill ----------------
__global__ void k_prefix() {
    __shared__ int sm[1024];
    int t = threadIdx.x;
    int my = g_icnt[t];
    sm[t] = my;
    __syncthreads();
    for (int o = 1; o < 1024; o <<= 1) {
        int v = (t >= o) ? sm[t - o] : 0;
        __syncthreads();
        sm[t] += v;
        __syncthreads();
    }
    g_cursor[t] = sm[t] - my;     // exclusive prefix
}

__global__ void k_fill() {
    int i = blockIdx.x * blockDim.x + threadIdx.x;   // 131072 threads
    int code = g_zid[i];
    int t = atomicAdd(&g_cursor[code], 1);
    g_csr[t] = i;
}

// gather-sum per code: block per code, thread per dim (coalesced row reads)
__global__ __launch_bounds__(256) void k_sum(const float* __restrict__ h) {
    int c = blockIdx.x, d = threadIdx.x;
    int cnt = g_icnt[c];
    int start = g_cursor[c] - cnt;   // cursor is end offset after fill
    float acc = 0.0f;
    int j = 0;
    for (; j + 4 <= cnt; j += 4) {
        int r0 = g_csr[start + j],     r1 = g_csr[start + j + 1];
        int r2 = g_csr[start + j + 2], r3 = g_csr[start + j + 3];
        float v0 = h[(size_t)r0 * DDIM + d];
        float v1 = h[(size_t)r1 * DDIM + d];
        float v2 = h[(size_t)r2 * DDIM + d];
        float v3 = h[(size_t)r3 * DDIM + d];
        acc += v0 + v1 + v2 + v3;
    }
    for (; j < cnt; j++) acc += h[(size_t)g_csr[start + j] * DDIM + d];
    g_esum[(size_t)c * DDIM + d] = acc;
}

// ---------------- per-row assign (pure streaming) ----------------
__global__ __launch_bounds__(256) void k_assign(const float* __restrict__ h,
                                                const float* __restrict__ embed,
                                                float* __restrict__ out) {
    __shared__ float wsum[8];
    int lane = threadIdx.x & 31, w = threadIdx.x >> 5;
    size_t row = (size_t)blockIdx.x * 8 + w;
    int code = g_zid[row];
    const float4* hr = (const float4*)(h + row * DDIM);
    const float4* er = (const float4*)(embed + (size_t)code * DDIM);
    float*  zq   = out + OFF_ZQ + row * DDIM;            // 4B-aligned only
    float4* zqst = (float4*)(out + OFF_ZQST + row * DDIM);
    float acc = 0.0f;
#pragma unroll
    for (int t = 0; t < 2; t++) {
        int d4 = lane + 32 * t;
        float4 hv = hr[d4], ev = er[d4];
        zq[d4 * 4 + 0] = ev.x; zq[d4 * 4 + 1] = ev.y;
        zq[d4 * 4 + 2] = ev.z; zq[d4 * 4 + 3] = ev.w;
        float4 st;
        st.x = hv.x + (ev.x - hv.x); st.y = hv.y + (ev.y - hv.y);
        st.z = hv.z + (ev.z - hv.z); st.w = hv.w + (ev.w - hv.w);
        zqst[d4] = st;
        float dx = hv.x - ev.x, dy = hv.y - ev.y, dz = hv.z - ev.z, dw = hv.w - ev.w;
        acc += dx * dx + dy * dy + dz * dz + dw * dw;
    }
#pragma unroll
    for (int o = 16; o; o >>= 1) acc += __shfl_xor_sync(0xFFFFFFFFu, acc, o);
    if (lane == 0) wsum[w] = acc;
    __syncthreads();
    if (threadIdx.x == 0) {
        double sum = 0.0;
#pragma unroll
        for (int i = 0; i < 8; i++) sum += (double)wsum[i];
        g_losspart[blockIdx.x] = sum;
    }
}

// ---------------- per-code scalars ----------------
__global__ void k_final_a(const float* __restrict__ cs_in, float* __restrict__ out) {
    __shared__ double sd[1024];
    int t = threadIdx.x;
    float c = (float)g_icnt[t];
    float ncs = cs_in[t] * DECAYC + c * (1.0f - DECAYC);

    sd[t] = (double)ncs; __syncthreads();
    for (int o = 512; o; o >>= 1) { if (t < o) sd[t] += sd[t + o]; __syncthreads(); }
    double n = sd[0]; __syncthreads();

    float usage = c / 131072.0f;
    float term = (usage > 0.0f) ? usage * logf(usage) : 0.0f;
    sd[t] = (double)term; __syncthreads();
    for (int o = 512; o; o >>= 1) { if (t < o) sd[t] += sd[t + o]; __syncthreads(); }
    float ent = -(float)sd[0]; __syncthreads();

    double lp = 0.0;
    for (int i = t; i < 16384; i += 1024) lp += g_losspart[i];
    sd[t] = lp; __syncthreads();
    for (int o = 512; o; o >>= 1) { if (t < o) sd[t] += sd[t + o]; __syncthreads(); }
    double loss_sum = sd[0];

    float nf = (float)n;
    float meanv = (float)(n / 1024.0);
    float cs_sm = (ncs + EPSC) / (nf + 1024.0f * EPSC) * nf;
    float den = fmaxf(cs_sm, EPSC);
    bool dead = (ncs / (131072.0f + EPSC)) < 0.01f;

    g_den[t] = den;
    g_src[t] = dead ? (int)jax_randint_idx(t) : -1;
    out[OFF_NCS + t] = dead ? fmaxf(meanv, 1.0f) : ncs;

    if (t == 0) {
        out[OFF_LOSS] = (float)(loss_sum / (double)((size_t)NROWS * DDIM));
        out[OFF_PPL]  = expf(ent);
    }
}

__global__ void k_final_b(const float* __restrict__ h, const float* __restrict__ ea_in,
                          float* __restrict__ out) {
    int k = blockIdx.x;
    int d = threadIdx.x;
    size_t idx = (size_t)k * DDIM + d;
    float nea = ea_in[idx] * DECAYC + g_esum[idx] * (1.0f - DECAYC);
    out[OFF_NEA + idx] = nea;
    int src = g_src[k];
    float ne = (src >= 0) ? h[(size_t)src * DDIM + d] : nea / g_den[k];
    out[OFF_NEMB + idx] = ne;
}

// ---------------- launch (graph-forked dual stream) ----------------
extern "C" void kernel_launch(void* const* d_in, const int* in_sizes, int n_in,
                              void* d_out, int out_size) {
    const float* h     = (const float*)d_in[0];
    const float* embed = (const float*)d_in[1];
    const float* cs    = (const float*)d_in[2];
    const float* ea    = (const float*)d_in[3];
    float* out = (float*)d_out;

    static int inited = 0;
    static cudaStream_t s2;
    static cudaEvent_t evFork, evPrep, evZid, evAssign;
    if (!inited) {
        cudaFuncSetAttribute(k_argmin_mma, cudaFuncAttributeMaxDynamicSharedMemorySize, SMEM_DYN);
        cudaStreamCreateWithFlags(&s2, cudaStreamNonBlocking);
        cudaEventCreateWithFlags(&evFork,   cudaEventDisableTiming);
        cudaEventCreateWithFlags(&evPrep,   cudaEventDisableTiming);
        cudaEventCreateWithFlags(&evZid,    cudaEventDisableTiming);
        cudaEventCreateWithFlags(&evAssign, cudaEventDisableTiming);
        inited = 1;
    }

    // fork: small prep on s2, big prep on main
    cudaEventRecord(evFork, 0);
    cudaStreamWaitEvent(s2, evFork, 0);
    k_zero<<<1, 1024, 0, s2>>>();
    k_prep_embed<<<128, 256, 0, s2>>>(embed);
    cudaEventRecord(evPrep, s2);

    k_prep_h<<<16384, 256>>>(h);
    cudaStreamWaitEvent(0, evPrep, 0);          // join before argmin

    k_argmin_mma<<<1024, 512, SMEM_DYN>>>(out);
    cudaEventRecord(evZid, 0);

    // fork: assign on s2 || CSR chain on main
    cudaStreamWaitEvent(s2, evZid, 0);
    k_assign<<<16384, 256, 0, s2>>>(h, embed, out);
    cudaEventRecord(evAssign, s2);

    k_prefix<<<1, 1024>>>();
    k_fill<<<512, 256>>>();
    k_sum<<<1024, 256>>>(h);

    cudaStreamWaitEvent(0, evAssign, 0);        // join before finals
    k_final_a<<<1, 1024>>>(cs, out);
    k_final_b<<<1024, 256>>>(h, ea, out);
}

// round 17
// speedup vs baseline: 1.0175x; 1.0175x over previous
#include <cuda_runtime.h>
#include <cuda_fp16.h>
#include <math.h>
#include <stdint.h>

// ---------------- problem constants ----------------
#define NROWS   131072
#define DDIM    256
#define NCODES  1024
#define EPSC    1e-5f
#define DECAYC  0.99f

// ---------------- output layout (float32, reference tuple order, flattened) ----------------
#define OFF_ZQST 0ULL
#define OFF_ZID  33554432ULL
#define OFF_LOSS 33685504ULL
#define OFF_ZQ   33685505ULL
#define OFF_NEMB 67239937ULL
#define OFF_NCS  67502081ULL
#define OFF_NEA  67503105ULL
#define OFF_PPL  67765249ULL

#define CORR_SCALE 1024.0f
#define CORR_INV   0.0009765625f   // 2^-10

// ---------------- device scratch (static: no allocation allowed) ----------------
static __device__ __half g_e0[NCODES * DDIM];   // fp16(normalized embed)
static __device__ __half g_e1[NCODES * DDIM];   // fp16((en - e0) * 2^10)
static __device__ int    g_zid[NROWS];
static __device__ int    g_icnt[NCODES];        // int histogram of z_id
static __device__ int    g_cursor[NCODES];      // prefix offsets -> end offsets
static __device__ int    g_csr[NROWS];          // row ids grouped by code
static __device__ float  g_esum[NCODES * DDIM];
static __device__ double g_losspart[16384];
static __device__ float  g_den[NCODES];
static __device__ int    g_src[NCODES];

// ---------------- smem layout for argmin kernel ----------------
// A persistent: [0, 131072)  4 kt-tiles x 2 splits x 16KB   (tile idx = kt*2+split)
// B stream:     [131072, 196608)  2 bufs x (2 splits x 16KB)
#define A_BASE   0u
#define B_BASE   131072u
#define RV_OFF   196608u
#define RI_OFF   198656u
#define SMEM_DYN 200704u

// ---------------- PTX helpers (baseline sm_80+ features only) ----------------
__device__ __forceinline__ uint32_t smem_u32(const void* p) {
    uint32_t a;
    asm("{ .reg .u64 t; cvta.to.shared.u64 t, %1; cvt.u32.u64 %0, t; }" : "=r"(a) : "l"(p));
    return a;
}
__device__ __forceinline__ void cpa16(uint32_t dst, const void* src) {
    asm volatile("cp.async.cg.shared.global [%0], [%1], 16;" :: "r"(dst), "l"(src) : "memory");
}
#define CP_COMMIT() asm volatile("cp.async.commit_group;" ::: "memory")
#define CP_WAIT0()  asm volatile("cp.async.wait_group 0;" ::: "memory")

__device__ __forceinline__ void ldmx4(uint32_t* r, uint32_t addr) {
    asm volatile("ldmatrix.sync.aligned.m8n8.x4.shared.b16 {%0,%1,%2,%3}, [%4];"
        : "=r"(r[0]), "=r"(r[1]), "=r"(r[2]), "=r"(r[3]) : "r"(addr));
}
__device__ __forceinline__ void hmma(float* c, const uint32_t* a, const uint32_t* b) {
    asm volatile("mma.sync.aligned.m16n8k16.row.col.f32.f16.f16.f32 "
        "{%0,%1,%2,%3}, {%4,%5,%6,%7}, {%8,%9}, {%0,%1,%2,%3};"
        : "+f"(c[0]), "+f"(c[1]), "+f"(c[2]), "+f"(c[3])
        : "r"(a[0]), "r"(a[1]), "r"(a[2]), "r"(a[3]), "r"(b[0]), "r"(b[1]));
}
// 16B-granule XOR swizzle within 128B rows (conflict-free ldmatrix)
__device__ __forceinline__ uint32_t swzoff(int r, int ci) {
    uint32_t o = (uint32_t)(r * 128 + ci * 16);
    return o ^ ((o >> 3) & 0x70);
}

// ---------------- threefry / jax randint ----------------
__device__ __forceinline__ unsigned rotl32(unsigned x, int r) { return (x << r) | (x >> (32 - r)); }
__device__ __forceinline__ void tf2x32(unsigned k0, unsigned k1, unsigned& x0, unsigned& x1) {
    const unsigned ks2 = 0x1BD11BDAu ^ k0 ^ k1;
#define TF_RND(r) { x0 += x1; x1 = rotl32(x1, (r)); x1 ^= x0; }
    x0 += k0; x1 += k1;
    TF_RND(13) TF_RND(15) TF_RND(26) TF_RND(6)
    x0 += k1;  x1 += ks2 + 1u;
    TF_RND(17) TF_RND(29) TF_RND(16) TF_RND(24)
    x0 += ks2; x1 += k0 + 2u;
    TF_RND(13) TF_RND(15) TF_RND(26) TF_RND(6)
    x0 += k0;  x1 += k1 + 3u;
    TF_RND(17) TF_RND(29) TF_RND(16) TF_RND(24)
    x0 += k1;  x1 += ks2 + 4u;
    TF_RND(13) TF_RND(15) TF_RND(26) TF_RND(6)
    x0 += ks2; x1 += k0 + 5u;
#undef TF_RND
}
__device__ unsigned jax_randint_idx(int i) {
    unsigned s0 = 0u, s1 = 1u;
    tf2x32(0u, 42u, s0, s1);
    unsigned x0 = 0u, x1 = (unsigned)i;
    tf2x32(s0, s1, x0, x1);
    return (x0 ^ x1) & 0x1FFFFu;
}

// ---------------- fp16 scaled double split ----------------
__device__ __forceinline__ void hsplit(float a, unsigned short& u0, unsigned short& u1) {
    __half p0 = __float2half_rn(a);
    float r = a - __half2float(p0);
    __half p1 = __float2half_rn(r * CORR_SCALE);
    u0 = __half_as_ushort(p0);
    u1 = __half_as_ushort(p1);
}

// ---------------- prep kernels ----------------
// normalize embed rows and write scaled fp16 splits; block 0 also zeroes g_icnt
__global__ void k_prep_embed(const float* __restrict__ e) {
    if (blockIdx.x == 0) {
        for (int i = threadIdx.x; i < NCODES; i += 256) g_icnt[i] = 0;
    }
    int w = (blockIdx.x * blockDim.x + threadIdx.x) >> 5;
    int lane = threadIdx.x & 31;
    if (w >= NCODES) return;
    const float* row = e + (size_t)w * DDIM;
    float s = 0.0f;
#pragma unroll
    for (int t = 0; t < 8; t++) { float v = row[lane + 32 * t]; s += v * v; }
#pragma unroll
    for (int o = 16; o; o >>= 1) s += __shfl_xor_sync(0xFFFFFFFFu, s, o);
    float rs = (float)(1.0 / sqrt((double)fmaxf(s, 1e-12f)));
#pragma unroll
    for (int t = 0; t < 8; t++) {
        int d = lane + 32 * t;
        unsigned short u0, u1;
        hsplit(row[d] * rs, u0, u1);
        size_t idx = (size_t)w * DDIM + d;
        g_e0[idx] = __ushort_as_half(u0);
        g_e1[idx] = __ushort_as_half(u1);
    }
}

// ---------------- HMMA argmin GEMM: in-kernel A prep (h->splits->smem), B streamed ----------------
__device__ __forceinline__ void issue_B(int tid, int s2, uint32_t smem_base) {
    const int cc = s2 >> 2, kt = s2 & 3;
    uint32_t buf = smem_base + B_BASE + (uint32_t)(s2 & 1) * 32768u;
    const __half* eb[2] = { g_e0, g_e1 };
#pragma unroll
    for (int t = 0; t < 2; t++) {
#pragma unroll
        for (int q = 0; q < 2; q++) {
            int idx = tid + 512 * q;           // 1024 granules of 16B per split
            int r = idx >> 3, ci = idx & 7;
            cpa16(buf + t * 16384u + swzoff(r, ci),
                  eb[t] + (size_t)(cc * 128 + r) * DDIM + kt * 64 + ci * 8);
        }
    }
}

__global__ __launch_bounds__(512, 1) void k_argmin_mma(const float* __restrict__ h,
                                                       float* __restrict__ out) {
    extern __shared__ __align__(1024) char smem[];
    const uint32_t sb = smem_u32(smem);
    const int tid = threadIdx.x, lane = tid & 31, w = tid >> 5;
    const size_t rowBase = (size_t)blockIdx.x * 128;

    // stage-0 B loads first (overlap with A prologue)
    issue_B(tid, 0, sb);
    CP_COMMIT();

    // --- prologue: normalize + split this CTA's 128 h rows into smem A tiles.
    // BIT-EXACT norm order (proven in R13): lane handles dims {4L..4L+3} (t=0)
    // and {128+4L..128+4L+3} (t=1); 16 warps x 8 rows each.
    {
        const int kt0 = lane >> 4;          // t=0 -> kt 0/1; t=1 -> kt 2/3
        const int ci  = (lane & 15) >> 1;   // 16B granule within tile row
        const int sub = (lane & 1) * 8;     // half-granule byte offset
#pragma unroll 1
        for (int rr = 0; rr < 8; rr++) {
            int row = w * 8 + rr;
            const float4* hp = (const float4*)(h + (rowBase + row) * DDIM);
            float4 v0 = hp[lane];
            float4 v1 = hp[lane + 32];
            float s = 0.0f;
            s += v0.x * v0.x + v0.y * v0.y + v0.z * v0.z + v0.w * v0.w;
            s += v1.x * v1.x + v1.y * v1.y + v1.z * v1.z + v1.w * v1.w;
#pragma unroll
            for (int o = 16; o; o >>= 1) s += __shfl_xor_sync(0xFFFFFFFFu, s, o);
            float rs = (float)(1.0 / sqrt((double)fmaxf(s, 1e-12f)));
            float a0[4] = { v0.x * rs, v0.y * rs, v0.z * rs, v0.w * rs };
            float a1[4] = { v1.x * rs, v1.y * rs, v1.z * rs, v1.w * rs };
            unsigned short p0[4], q0[4], p1[4], q1[4];
#pragma unroll
            for (int e = 0; e < 4; e++) { hsplit(a0[e], p0[e], q0[e]); hsplit(a1[e], p1[e], q1[e]); }
            uint32_t sw = swzoff(row, ci) + sub;
            uint32_t b0 = A_BASE + (uint32_t)(kt0 * 2) * 16384u;          // kt=kt0
            uint32_t b1 = A_BASE + (uint32_t)((2 + kt0) * 2) * 16384u;    // kt=2+kt0
            *(uint2*)(smem + b0 + sw) =
                make_uint2((uint32_t)p0[0] | ((uint32_t)p0[1] << 16),
                           (uint32_t)p0[2] | ((uint32_t)p0[3] << 16));
            *(uint2*)(smem + b0 + 16384u + sw) =
                make_uint2((uint32_t)q0[0] | ((uint32_t)q0[1] << 16),
                           (uint32_t)q0[2] | ((uint32_t)q0[3] << 16));
            *(uint2*)(smem + b1 + sw) =
                make_uint2((uint32_t)p1[0] | ((uint32_t)p1[1] << 16),
                           (uint32_t)p1[2] | ((uint32_t)p1[3] << 16));
            *(uint2*)(smem + b1 + 16384u + sw) =
                make_uint2((uint32_t)q1[0] | ((uint32_t)q1[1] << 16),
                           (uint32_t)q1[2] | ((uint32_t)q1[3] << 16));
        }
    }
    CP_WAIT0();
    __syncthreads();

    const int mbase = (w & 3) * 32;    // warp's 32 rows within 128
    const int nbw   = (w >> 2) * 32;   // warp's 32 codes within 128-chunk

    float accM[2][4][4], accC[2][4][4];
    float bestV[4]; int bestI[4];
#pragma unroll
    for (int b = 0; b < 4; b++) { bestV[b] = 3.4e38f; bestI[b] = 0; }

    const int arow = mbase + (lane & 7) + ((lane >> 3) & 1) * 8;
    const int aciX = (lane >> 4);
    const int brow = nbw + (lane & 7) + ((lane >> 4) << 3);
    const int bciX = ((lane >> 3) & 1);

    for (int s = 0; s < 32; s++) {              // s = cc*4 + kt
        const uint32_t bufB = sb + B_BASE + (uint32_t)(s & 1) * 32768u;
        const uint32_t bufA = sb + A_BASE + (uint32_t)((s & 3) * 2) * 16384u;
        if ((s & 3) == 0) {
#pragma unroll
            for (int mi = 0; mi < 2; mi++)
#pragma unroll
                for (int nj = 0; nj < 4; nj++)
#pragma unroll
                    for (int rr = 0; rr < 4; rr++) { accM[mi][nj][rr] = 0.0f; accC[mi][nj][rr] = 0.0f; }
        }
        if (s < 31) {
            issue_B(tid, s + 1, sb);
            CP_COMMIT();
        }

#pragma unroll
        for (int ks = 0; ks < 4; ks++) {
            uint32_t Aoff = swzoff(arow, ks * 2 + aciX);
            uint32_t A[2][2][4];
#pragma unroll
            for (int t = 0; t < 2; t++) {
                ldmx4(A[t][0], bufA + t * 16384u + Aoff);
                ldmx4(A[t][1], bufA + t * 16384u + Aoff + 2048u);
            }
            uint32_t Boff = swzoff(brow, ks * 2 + bciX);
            uint32_t B0a[4], B0b[4], B1a[4], B1b[4];
            ldmx4(B0a, bufB + Boff);
            ldmx4(B0b, bufB + Boff + 2048u);
            ldmx4(B1a, bufB + 16384u + Boff);
            ldmx4(B1b, bufB + 16384u + Boff + 2048u);
#pragma unroll
            for (int nj = 0; nj < 4; nj++) {
                const uint32_t* b0 = (nj < 2 ? B0a : B0b) + (nj & 1) * 2;
                const uint32_t* b1 = (nj < 2 ? B1a : B1b) + (nj & 1) * 2;
#pragma unroll
                for (int mi = 0; mi < 2; mi++) {
                    hmma(accM[mi][nj], A[0][mi], b0);
                    hmma(accC[mi][nj], A[0][mi], b1);
                    hmma(accC[mi][nj], A[1][mi], b0);
                }
            }
        }

        if ((s & 3) == 3) {                 // chunk done: fold argmin
            const int cc = s >> 2;
#pragma unroll
            for (int mi = 0; mi < 2; mi++)
#pragma unroll
                for (int nj = 0; nj < 4; nj++) {
                    int col0 = cc * 128 + nbw + nj * 8 + (lane & 3) * 2;
                    float d0 = 1.0f - (accM[mi][nj][0] + accC[mi][nj][0] * CORR_INV);
                    float d1 = 1.0f - (accM[mi][nj][1] + accC[mi][nj][1] * CORR_INV);
                    float d2 = 1.0f - (accM[mi][nj][2] + accC[mi][nj][2] * CORR_INV);
                    float d3 = 1.0f - (accM[mi][nj][3] + accC[mi][nj][3] * CORR_INV);
                    int b0 = 2 * mi, b1 = 2 * mi + 1;
                    if (d0 < bestV[b0]) { bestV[b0] = d0; bestI[b0] = col0; }
                    if (d1 < bestV[b0]) { bestV[b0] = d1; bestI[b0] = col0 + 1; }
                    if (d2 < bestV[b1]) { bestV[b1] = d2; bestI[b1] = col0; }
                    if (d3 < bestV[b1]) { bestV[b1] = d3; bestI[b1] = col0 + 1; }
                }
        }

        if (s < 31) { CP_WAIT0(); __syncthreads(); }
    }

    // quad reduce: lanes 4q..4q+3 share the same rows, different cols
#pragma unroll
    for (int off = 1; off <= 2; off <<= 1) {
#pragma unroll
        for (int b = 0; b < 4; b++) {
            float v = __shfl_down_sync(0xFFFFFFFFu, bestV[b], off);
            int   i = __shfl_down_sync(0xFFFFFFFFu, bestI[b], off);
            if (v < bestV[b] || (v == bestV[b] && i < bestI[b])) { bestV[b] = v; bestI[b] = i; }
        }
    }
    float* redV = (float*)(smem + RV_OFF);          // 128 rows x 4 nwarps
    int*   redI = (int*)(smem + RI_OFF);
    if ((lane & 3) == 0) {
#pragma unroll
        for (int b = 0; b < 4; b++) {
            int row = mbase + (b >> 1) * 16 + (lane >> 2) + (b & 1) * 8;
            int nw = w >> 2;
            redV[row * 4 + nw] = bestV[b];
            redI[row * 4 + nw] = bestI[b];
        }
    }
    __syncthreads();
    if (tid < 128) {
        float bv = redV[tid * 4]; int bi = redI[tid * 4];
#pragma unroll
        for (int t = 1; t < 4; t++) {
            float v = redV[tid * 4 + t]; int ix = redI[tid * 4 + t];
            if (v < bv || (v == bv && ix < bi)) { bv = v; bi = ix; }
        }
        g_zid[rowBase + tid] = bi;
        out[OFF_ZID + rowBase + tid] = (float)bi;
        atomicAdd(&g_icnt[bi], 1);      // fused count
    }
}

// ---------------- CSR build: prefix -> fill ----------------
__global__ void k_prefix() {
    __shared__ int sm[1024];
    int t = threadIdx.x;
    int my = g_icnt[t];
    sm[t] = my;
    __syncthreads();
    for (int o = 1; o < 1024; o <<= 1) {
        int v = (t >= o) ? sm[t - o] : 0;
        __syncthreads();
        sm[t] += v;
        __syncthreads();
    }
    g_cursor[t] = sm[t] - my;     // exclusive prefix
}

__global__ void k_fill() {
    int i = blockIdx.x * blockDim.x + threadIdx.x;   // 131072 threads
    int code = g_zid[i];
    int t = atomicAdd(&g_cursor[code], 1);
    g_csr[t] = i;
}

// gather-sum per code: block per code, thread per dim (coalesced row reads)
__global__ __launch_bounds__(256) void k_sum(const float* __restrict__ h) {
    int c = blockIdx.x, d = threadIdx.x;
    int cnt = g_icnt[c];
    int start = g_cursor[c] - cnt;   // cursor is end offset after fill
    float acc = 0.0f;
    int j = 0;
    for (; j + 4 <= cnt; j += 4) {
        int r0 = g_csr[start + j],     r1 = g_csr[start + j + 1];
        int r2 = g_csr[start + j + 2], r3 = g_csr[start + j + 3];
        float v0 = h[(size_t)r0 * DDIM + d];
        float v1 = h[(size_t)r1 * DDIM + d];
        float v2 = h[(size_t)r2 * DDIM + d];
        float v3 = h[(size_t)r3 * DDIM + d];
        acc += v0 + v1 + v2 + v3;
    }
    for (; j < cnt; j++) acc += h[(size_t)g_csr[start + j] * DDIM + d];
    g_esum[(size_t)c * DDIM + d] = acc;
}

// ---------------- per-row assign (pure streaming) ----------------
__global__ __launch_bounds__(256) void k_assign(const float* __restrict__ h,
                                                const float* __restrict__ embed,
                                                float* __restrict__ out) {
    __shared__ float wsum[8];
    int lane = threadIdx.x & 31, w = threadIdx.x >> 5;
    size_t row = (size_t)blockIdx.x * 8 + w;
    int code = g_zid[row];
    const float4* hr = (const float4*)(h + row * DDIM);
    const float4* er = (const float4*)(embed + (size_t)code * DDIM);
    float*  zq   = out + OFF_ZQ + row * DDIM;            // 4B-aligned only
    float4* zqst = (float4*)(out + OFF_ZQST + row * DDIM);
    float acc = 0.0f;
#pragma unroll
    for (int t = 0; t < 2; t++) {
        int d4 = lane + 32 * t;
        float4 hv = hr[d4], ev = er[d4];
        zq[d4 * 4 + 0] = ev.x; zq[d4 * 4 + 1] = ev.y;
        zq[d4 * 4 + 2] = ev.z; zq[d4 * 4 + 3] = ev.w;
        float4 st;
        st.x = hv.x + (ev.x - hv.x); st.y = hv.y + (ev.y - hv.y);
        st.z = hv.z + (ev.z - hv.z); st.w = hv.w + (ev.w - hv.w);
        zqst[d4] = st;
        float dx = hv.x - ev.x, dy = hv.y - ev.y, dz = hv.z - ev.z, dw = hv.w - ev.w;
        acc += dx * dx + dy * dy + dz * dz + dw * dw;
    }
#pragma unroll
    for (int o = 16; o; o >>= 1) acc += __shfl_xor_sync(0xFFFFFFFFu, acc, o);
    if (lane == 0) wsum[w] = acc;
    __syncthreads();
    if (threadIdx.x == 0) {
        double sum = 0.0;
#pragma unroll
        for (int i = 0; i < 8; i++) sum += (double)wsum[i];
        g_losspart[blockIdx.x] = sum;
    }
}

// ---------------- per-code scalars ----------------
__global__ void k_final_a(const float* __restrict__ cs_in, float* __restrict__ out) {
    __shared__ double sd[1024];
    int t = threadIdx.x;
    float c = (float)g_icnt[t];
    float ncs = cs_in[t] * DECAYC + c * (1.0f - DECAYC);

    sd[t] = (double)ncs; __syncthreads();
    for (int o = 512; o; o >>= 1) { if (t < o) sd[t] += sd[t + o]; __syncthreads(); }
    double n = sd[0]; __syncthreads();

    float usage = c / 131072.0f;
    float term = (usage > 0.0f) ? usage * logf(usage) : 0.0f;
    sd[t] = (double)term; __syncthreads();
    for (int o = 512; o; o >>= 1) { if (t < o) sd[t] += sd[t + o]; __syncthreads(); }
    float ent = -(float)sd[0]; __syncthreads();

    double lp = 0.0;
    for (int i = t; i < 16384; i += 1024) lp += g_losspart[i];
    sd[t] = lp; __syncthreads();
    for (int o = 512; o; o >>= 1) { if (t < o) sd[t] += sd[t + o]; __syncthreads(); }
    double loss_sum = sd[0];

    float nf = (float)n;
    float meanv = (float)(n / 1024.0);
    float cs_sm = (ncs + EPSC) / (nf + 1024.0f * EPSC) * nf;
    float den = fmaxf(cs_sm, EPSC);
    bool dead = (ncs / (131072.0f + EPSC)) < 0.01f;

    g_den[t] = den;
    g_src[t] = dead ? (int)jax_randint_idx(t) : -1;
    out[OFF_NCS + t] = dead ? fmaxf(meanv, 1.0f) : ncs;

    if (t == 0) {
        out[OFF_LOSS] = (float)(loss_sum / (double)((size_t)NROWS * DDIM));
        out[OFF_PPL]  = expf(ent);
    }
}

__global__ void k_final_b(const float* __restrict__ h, const float* __restrict__ ea_in,
                          float* __restrict__ out) {
    int k = blockIdx.x;
    int d = threadIdx.x;
    size_t idx = (size_t)k * DDIM + d;
    float nea = ea_in[idx] * DECAYC + g_esum[idx] * (1.0f - DECAYC);
    out[OFF_NEA + idx] = nea;
    int src = g_src[k];
    float ne = (src >= 0) ? h[(size_t)src * DDIM + d] : nea / g_den[k];
    out[OFF_NEMB + idx] = ne;
}

// ---------------- launch ----------------
extern "C" void kernel_launch(void* const* d_in, const int* in_sizes, int n_in,
                              void* d_out, int out_size) {
    const float* h     = (const float*)d_in[0];
    const float* embed = (const float*)d_in[1];
    const float* cs    = (const float*)d_in[2];
    const float* ea    = (const float*)d_in[3];
    float* out = (float*)d_out;

    static int smem_set = 0;
    if (!smem_set) {
        cudaFuncSetAttribute(k_argmin_mma, cudaFuncAttributeMaxDynamicSharedMemorySize, SMEM_DYN);
        smem_set = 1;
    }

    k_prep_embed<<<128, 256>>>(embed);
    k_argmin_mma<<<1024, 512, SMEM_DYN>>>(h, out);
    k_prefix<<<1, 1024>>>();
    k_fill<<<512, 256>>>();
    k_sum<<<1024, 256>>>(h);
    k_assign<<<16384, 256>>>(h, embed, out);
    k_final_a<<<1, 1024>>>(cs, out);
    k_final_b<<<1024, 256>>>(h, ea, out);
}